// round 16
// baseline (speedup 1.0000x reference)
#include <cuda_runtime.h>
#include <cuda_fp16.h>
#include <stdint.h>

#define FF 64
#define HH 128
#define NROW 8192
#define FH 32
#define BSLAB 32768           // B slab: 128 n-rows * 256B, swizzled
#define ASLAB 16384           // A tile: 128 h-rows * 128B, swizzled

__device__ float g_gbuf[NROW * FF];     // raw gating logits
__device__ float g_wt_buf[NROW * FF];   // softmaxed gates (written by combine)
__device__ float g_part[NROW * HH];     // f-half-1 partial
__device__ __align__(16) unsigned char g_Bt[FF * BSLAB];  // jw3^T fp16 [f][n][h], swizzled

// ---------------- helpers ----------------
__device__ __forceinline__ uint32_t smem_u32(const void* p) {
    uint32_t a;
    asm("{ .reg .u64 t; cvta.to.shared.u64 t, %1; cvt.u32.u64 %0, t; }" : "=r"(a) : "l"(p));
    return a;
}
__device__ __forceinline__ void ffma2(unsigned long long& d, unsigned long long a, unsigned long long b) {
    asm("fma.rn.f32x2 %0, %1, %2, %0;" : "+l"(d) : "l"(a), "l"(b));
}
__device__ __forceinline__ unsigned long long pk2(float v) {
    unsigned long long r; asm("mov.b64 %0, {%1, %1};" : "=l"(r) : "f"(v)); return r;
}
__device__ __forceinline__ void up2(unsigned long long v, float& lo, float& hi) {
    asm("mov.b64 {%0, %1}, %2;" : "=f"(lo), "=f"(hi) : "l"(v));
}
#define CP16(dst, src)  asm volatile("cp.async.cg.shared.global [%0], [%1], 16;" :: "r"((uint32_t)(dst)), "l"(src) : "memory")
#define CP_COMMIT()     asm volatile("cp.async.commit_group;" ::: "memory")
#define CP_WAIT0()      asm volatile("cp.async.wait_group 0;" ::: "memory")

// swizzles: A rows are 128B (h-major), B rows are 256B (n-major)
#define SWZA(o) ((o) ^ ((((o) >> 7) & 7) << 4))
#define SWZB(o) ((o) ^ ((((o) >> 8) & 7) << 4))

__device__ __forceinline__ void ldsm4t(uint32_t& r0, uint32_t& r1, uint32_t& r2, uint32_t& r3, uint32_t a) {
    asm volatile("ldmatrix.sync.aligned.m8n8.x4.trans.shared.b16 {%0,%1,%2,%3}, [%4];"
                 : "=r"(r0), "=r"(r1), "=r"(r2), "=r"(r3) : "r"(a));
}
__device__ __forceinline__ void ldsm4(uint32_t& r0, uint32_t& r1, uint32_t& r2, uint32_t& r3, uint32_t a) {
    asm volatile("ldmatrix.sync.aligned.m8n8.x4.shared.b16 {%0,%1,%2,%3}, [%4];"
                 : "=r"(r0), "=r"(r1), "=r"(r2), "=r"(r3) : "r"(a));
}
__device__ __forceinline__ void mma16816(float* c, uint32_t a0, uint32_t a1, uint32_t a2, uint32_t a3,
                                         uint32_t b0, uint32_t b1) {
    asm volatile("mma.sync.aligned.m16n8k16.row.col.f32.f16.f16.f32 "
                 "{%0,%1,%2,%3}, {%4,%5,%6,%7}, {%8,%9}, {%0,%1,%2,%3};"
                 : "+f"(c[0]), "+f"(c[1]), "+f"(c[2]), "+f"(c[3])
                 : "r"(a0), "r"(a1), "r"(a2), "r"(a3), "r"(b0), "r"(b1));
}

// ---------------------------------------------------------------------------
// prep_gating: grid 128, one wave. Blocks 0-63 first do prep for f=blockIdx
// (scratch = w3s smem region, staged with w3 only afterwards), then ALL
// blocks run gating for rows [blockIdx*64, +64).
// Gating smem (164 KB, 1 CTA/SM):
//   xT 0 | sT 4096 | w1s 8192 | w2s 16384 | G1T 24576 (pitch 72) | w3s 33792
// ---------------------------------------------------------------------------
#define SMEMG 167936

__global__ __launch_bounds__(256) void prep_gating_kernel(
    const float* __restrict__ jw3,
    const float* __restrict__ x, const float* __restrict__ s,
    const float* __restrict__ w1, const float* __restrict__ b1,
    const float* __restrict__ w2, const float* __restrict__ b2,
    const float* __restrict__ w3, const float* __restrict__ b3)
{
    extern __shared__ float gm[];
    const int tid = threadIdx.x;

    if (blockIdx.x < 64) {
        // ---- prep: jw3[f][h][k] -> g_Bt[f][n=k][h] fp16, swizzled ----
        // scratch = w3s region (gm + 33792 floats), 32 KB
        char* psm = (char*)(gm + 33792);
        const int f = blockIdx.x;
        const int h = tid >> 1, khalf = tid & 1;
        #pragma unroll 4
        for (int j = 0; j < 16; j++) {
            float4 v = *(const float4*)(jw3 + f * 16384 + h * 128 + khalf * 64 + j * 4);
            int k0 = khalf * 64 + j * 4;
            float vv[4] = {v.x, v.y, v.z, v.w};
            #pragma unroll
            for (int e = 0; e < 4; e++) {
                uint32_t off = (uint32_t)(k0 + e) * 256u + (uint32_t)h * 2u;
                *(__half*)(psm + SWZB(off)) = __float2half_rn(vv[e]);
            }
        }
        __syncthreads();
        float4* dst = (float4*)(g_Bt + f * BSLAB);
        const float4* src = (const float4*)psm;
        #pragma unroll
        for (int i = 0; i < 8; i++)
            dst[tid + i * 256] = src[tid + i * 256];
        __syncthreads();   // prep done; w3s region free for w3 staging
    }

    // ---- gating: 64 rows -> raw logits g_gbuf ----
    float* xT  = gm;             // [64 f][64 r]
    float* sT  = gm + 4096;
    float* w1s = gm + 8192;      // [64 f][128 h]
    float* w2s = gm + 16384;
    float* G1T = gm + 24576;     // [128 h][72]
    float* w3s = gm + 33792;     // [128 h][64 f]
    const int rbase = blockIdx.x * 64;
    const int ty = tid >> 4, tx = tid & 15;

    // cp.async w1/w2/w3 -> smem (96 KB total)
    {
        const uint32_t smw = smem_u32(gm) + 32768u;     // w1s byte base
        const uint32_t smw3 = smem_u32(gm) + 135168u;   // w3s byte base
        #pragma unroll
        for (int i = 0; i < 8; i++) {
            CP16(smw + (uint32_t)(tid + i * 256) * 16u, (const char*)w1 + (tid + i * 256) * 16);
            CP16(smw + 32768u + (uint32_t)(tid + i * 256) * 16u, (const char*)w2 + (tid + i * 256) * 16);
            CP16(smw3 + (uint32_t)(tid + i * 256) * 16u, (const char*)w3 + (tid + i * 256) * 16);
        }
        CP_COMMIT();
    }
    #pragma unroll
    for (int i = 0; i < 4; i++) {
        int q = tid + i * 256;
        int r = q >> 4, fc = q & 15;
        float4 xv = *(const float4*)(x + (rbase + r) * FF + fc * 4);
        float4 sv = *(const float4*)(s + (rbase + r) * FF + fc * 4);
        xT[(fc * 4 + 0) * 64 + r] = xv.x; xT[(fc * 4 + 1) * 64 + r] = xv.y;
        xT[(fc * 4 + 2) * 64 + r] = xv.z; xT[(fc * 4 + 3) * 64 + r] = xv.w;
        sT[(fc * 4 + 0) * 64 + r] = sv.x; sT[(fc * 4 + 1) * 64 + r] = sv.y;
        sT[(fc * 4 + 2) * 64 + r] = sv.z; sT[(fc * 4 + 3) * 64 + r] = sv.w;
    }
    CP_WAIT0();
    __syncthreads();

    unsigned long long acc[2][8];
    #pragma unroll
    for (int i = 0; i < 2; i++)
        #pragma unroll
        for (int j = 0; j < 8; j++) acc[i][j] = 0ull;

    #pragma unroll 4
    for (int f = 0; f < FF; f++) {
        ulonglong2 xv = *(const ulonglong2*)(xT + f * 64 + ty * 4);
        ulonglong2 sv = *(const ulonglong2*)(sT + f * 64 + ty * 4);
        float4 wa = *(const float4*)(w1s + f * HH + tx * 8);
        float4 wb = *(const float4*)(w1s + f * HH + tx * 8 + 4);
        float4 va = *(const float4*)(w2s + f * HH + tx * 8);
        float4 vb = *(const float4*)(w2s + f * HH + tx * 8 + 4);
        float ws[8] = {wa.x, wa.y, wa.z, wa.w, wb.x, wb.y, wb.z, wb.w};
        float vs[8] = {va.x, va.y, va.z, va.w, vb.x, vb.y, vb.z, vb.w};
        unsigned long long xp[2] = {xv.x, xv.y}, sp[2] = {sv.x, sv.y};
        #pragma unroll
        for (int j = 0; j < 8; j++) {
            unsigned long long wj = pk2(ws[j]), vj = pk2(vs[j]);
            #pragma unroll
            for (int i = 0; i < 2; i++) { ffma2(acc[i][j], xp[i], wj); ffma2(acc[i][j], sp[i], vj); }
        }
    }
    #pragma unroll
    for (int j = 0; j < 8; j++) {
        int h = tx * 8 + j;
        float bb = b1[h] + b2[h];
        float v[4];
        up2(acc[0][j], v[0], v[1]); up2(acc[1][j], v[2], v[3]);
        float4 o; float* po = &o.x;
        #pragma unroll
        for (int i = 0; i < 4; i++) {
            float t = v[i] + bb;
            po[i] = t > 0.f ? t : (__expf(t) - 1.f);
        }
        *(float4*)(G1T + h * 72 + ty * 4) = o;
    }
    __syncthreads();

    unsigned long long a2[2][4];
    #pragma unroll
    for (int i = 0; i < 2; i++)
        #pragma unroll
        for (int j = 0; j < 4; j++) a2[i][j] = 0ull;
    #pragma unroll 8
    for (int h = 0; h < HH; h++) {
        ulonglong2 av = *(const ulonglong2*)(G1T + h * 72 + ty * 4);
        float4 wv = *(const float4*)(w3s + h * FF + tx * 4);
        float ws[4] = {wv.x, wv.y, wv.z, wv.w};
        unsigned long long ap[2] = {av.x, av.y};
        #pragma unroll
        for (int j = 0; j < 4; j++) {
            unsigned long long wj = pk2(ws[j]);
            ffma2(a2[0][j], ap[0], wj);
            ffma2(a2[1][j], ap[1], wj);
        }
    }
    float b3v[4] = {b3[tx * 4], b3[tx * 4 + 1], b3[tx * 4 + 2], b3[tx * 4 + 3]};
    #pragma unroll
    for (int p = 0; p < 2; p++) {
        float lo[4], hi[4];
        #pragma unroll
        for (int j = 0; j < 4; j++) up2(a2[p][j], lo[j], hi[j]);
        int r0 = rbase + ty * 4 + p * 2;
        *(float4*)(g_gbuf + r0 * FF + tx * 4) =
            make_float4(lo[0] + b3v[0], lo[1] + b3v[1], lo[2] + b3v[2], lo[3] + b3v[3]);
        *(float4*)(g_gbuf + (r0 + 1) * FF + tx * 4) =
            make_float4(hi[0] + b3v[0], hi[1] + b3v[1], hi[2] + b3v[2], hi[3] + b3v[3]);
    }
}

// ---------------------------------------------------------------------------
// combine: grid 256 = 128 row-tiles x 2 f-halves, 64 rows, 32 f. 2 CTAs/SM.
// Softmax fused (stages logits into A-buf0 window before first A build).
// smem: A 2x16384 | B 2x32768 | XS 8192 | WT 4096 (fp16) | JWC 2x1024
// ---------------------------------------------------------------------------
#define AB_OFF  0u
#define BB_OFF  32768u
#define XS_OFF  98304u
#define WT_OFF  106496u
#define JW_OFF  110592u
#define SMEM2   112640u

__global__ __launch_bounds__(256, 2) void combine_kernel(
    const float* __restrict__ x,
    const float* __restrict__ jw1, const float* __restrict__ jb1,
    float* __restrict__ out)
{
    extern __shared__ char cm[];
    const uint32_t smb = smem_u32(cm);
    float* xs = (float*)(cm + XS_OFF);       // [32 f][64 r] fp32
    __half* wts = (__half*)(cm + WT_OFF);    // [32 f][64 r] fp16
    const int tid = threadIdx.x;
    const int wid = tid >> 5, lane = tid & 31;
    const int rt = blockIdx.x >> 1, half = blockIdx.x & 1;
    const int rbase = rt * 64, fbase = half * FH;
    const int gbase = (blockIdx.x >> 2) * 128;   // (b,a) group row base
    const int rhalf = rt & 1;                    // which 64-row half of the group
    float* dst = half ? g_part : out;

    // B(0) async copy
    {
        const unsigned char* src = g_Bt + fbase * BSLAB;
        #pragma unroll
        for (int i = 0; i < 8; i++)
            CP16(smb + BB_OFF + (tid + i * 256) * 16, src + (tid + i * 256) * 16);
        CP_COMMIT();
    }
    // stage raw logit column [32 f][128 t] into A-buf0 window (fp32, 16KB)
    {
        float* gcol = (float*)(cm + AB_OFF);
        #pragma unroll
        for (int i = 0; i < 4; i++) {
            int q = tid + i * 256;               // 0..1023
            int r = q >> 3, fs = q & 7;
            float4 gv = *(const float4*)(g_gbuf + (gbase + r) * FF + fbase + fs * 4);
            gcol[(fs * 4 + 0) * 128 + r] = gv.x;
            gcol[(fs * 4 + 1) * 128 + r] = gv.y;
            gcol[(fs * 4 + 2) * 128 + r] = gv.z;
            gcol[(fs * 4 + 3) * 128 + r] = gv.w;
        }
    }
    // stage xs (fp32) transposed [f][r]
    #pragma unroll
    for (int i = 0; i < 2; i++) {
        int q = tid + i * 256;               // 0..511
        int r = q >> 3, fs = q & 7;
        float4 xv = *(const float4*)(x + (rbase + r) * FF + fbase + fs * 4);
        xs[(fs * 4 + 0) * 64 + r] = xv.x; xs[(fs * 4 + 1) * 64 + r] = xv.y;
        xs[(fs * 4 + 2) * 64 + r] = xv.z; xs[(fs * 4 + 3) * 64 + r] = xv.w;
    }
    // jwc(0), jwc(1)
    if (tid < 128) {
        float* j0 = (float*)(cm + JW_OFF);
        float* j1 = (float*)(cm + JW_OFF + 1024);
        j0[2 * tid]     = jw1[(fbase + 0) * HH + tid];
        j0[2 * tid + 1] = jb1[(fbase + 0) * HH + tid];
        j1[2 * tid]     = jw1[(fbase + 1) * HH + tid];
        j1[2 * tid + 1] = jb1[(fbase + 1) * HH + tid];
    }
    __syncthreads();

    // fused softmax over 128 t per f (32 f x 8 lanes, 16 t each)
    {
        const float* gcol = (const float*)(cm + AB_OFF);
        const int fc = tid >> 3, sub = tid & 7;
        float vals[16], m = -1e30f;
        #pragma unroll
        for (int j = 0; j < 16; j++) {
            vals[j] = gcol[fc * 128 + sub * 16 + j];
            m = fmaxf(m, vals[j]);
        }
        #pragma unroll
        for (int o = 1; o < 8; o <<= 1) m = fmaxf(m, __shfl_xor_sync(0xffffffffu, m, o, 8));
        float ssum = 0.f;
        #pragma unroll
        for (int j = 0; j < 16; j++) { vals[j] = __expf(vals[j] - m); ssum += vals[j]; }
        #pragma unroll
        for (int o = 1; o < 8; o <<= 1) ssum += __shfl_xor_sync(0xffffffffu, ssum, o, 8);
        float rinv = 1.f / ssum;
        #pragma unroll
        for (int j = 0; j < 16; j++) {
            int t = sub * 16 + j;
            if ((t >> 6) == rhalf) {
                float w = vals[j] * rinv;
                wts[fc * 64 + (t & 63)] = __float2half_rn(w);
                g_wt_buf[(gbase + t) * FF + fbase + fc] = w;
            }
        }
    }
    __syncthreads();   // gcol reads done; A-buf0 free

    const int rp = tid & 31, hblk = tid >> 5;   // rows 2rp,2rp+1 ; h = hblk*16..
    // build A(0) into buf 0 (layout [h][r] fp16, swizzled 128B rows)
    {
        const float* jw = (const float*)(cm + JW_OFF);
        float2 xv = *(const float2*)(xs + 2 * rp);
        __half2 wh = *(__half2*)(wts + 2 * rp);
        float2 wv = __half22float2(wh);
        #pragma unroll 8
        for (int j = 0; j < 16; j++) {
            int h = hblk * 16 + j;
            float2 jv = *(const float2*)(jw + 2 * h);
            float v0 = fmaf(xv.x, jv.x, jv.y);
            float v1 = fmaf(xv.y, jv.x, jv.y);
            float a0 = (v0 > 0.f ? v0 : (__expf(v0) - 1.f)) * wv.x;
            float a1 = (v1 > 0.f ? v1 : (__expf(v1) - 1.f)) * wv.y;
            uint32_t off = (uint32_t)h * 128u + (uint32_t)rp * 4u;
            *(__half2*)(cm + AB_OFF + SWZA(off)) = __float22half2_rn(make_float2(a0, a1));
        }
    }
    CP_WAIT0();

    // ---- MMA geometry: 2 m-groups x 4 n-groups, precomputed swizzled cols ----
    const int mg = wid & 1, ng = wid >> 1;
    const int m0 = mg * 32, n0 = ng * 32;
    const int lr = lane & 7, sel0 = (lane >> 3) & 1, sel1 = (lane >> 4) & 1;
    const uint32_t aRow = (uint32_t)(sel1 * 8 + lr) * 128u;
    const uint32_t aXor = (uint32_t)lr << 4;
    const uint32_t aCol0 = ((uint32_t)(m0 * 2 + sel0 * 16)) ^ aXor;
    const uint32_t aCol1 = ((uint32_t)(m0 * 2 + 32 + sel0 * 16)) ^ aXor;
    const uint32_t bRow = (uint32_t)(lr + sel1 * 8 + n0);
    const uint32_t bXor = (bRow & 7u) << 4;
    const uint32_t bRowOff = bRow * 256u;
    uint32_t bCol[8];
    #pragma unroll
    for (int k = 0; k < 8; k++)
        bCol[k] = (((uint32_t)(sel0 * 16)) + (uint32_t)k * 32u) ^ bXor;

    float c[8][4];
    #pragma unroll
    for (int n = 0; n < 8; n++)
        #pragma unroll
        for (int e = 0; e < 4; e++) c[n][e] = 0.f;

    for (int fl = 0; fl < FH; fl++) {
        __syncthreads();   // A(fl) built, B(fl) arrived
        // stage jwc(fl+2)
        if (fl < FH - 2 && tid < 128) {
            float* jn = (float*)(cm + JW_OFF + (uint32_t)(fl & 1) * 1024);
            jn[2 * tid]     = jw1[(fbase + fl + 2) * HH + tid];
            jn[2 * tid + 1] = jb1[(fbase + fl + 2) * HH + tid];
        }
        // prefetch B(fl+1)
        if (fl < FH - 1) {
            const unsigned char* src = g_Bt + (fbase + fl + 1) * BSLAB;
            uint32_t dstb = smb + BB_OFF + (uint32_t)((fl + 1) & 1) * BSLAB;
            #pragma unroll
            for (int i = 0; i < 8; i++)
                CP16(dstb + (tid + i * 256) * 16, src + (tid + i * 256) * 16);
            CP_COMMIT();
        }

        // MMA(fl): k-major, 4 loads + 8 HMMA per k
        {
            const uint32_t aBase = smb + AB_OFF + (uint32_t)(fl & 1) * ASLAB + aRow;
            const uint32_t bBase = smb + BB_OFF + (uint32_t)(fl & 1) * BSLAB + bRowOff;
            #pragma unroll
            for (int k = 0; k < 8; k++) {
                uint32_t a0[4], a1[4], b0[4], b1[4];
                const uint32_t ak = aBase + (uint32_t)k * 2048u;
                ldsm4t(a0[0], a0[1], a0[2], a0[3], ak + aCol0);
                ldsm4t(a1[0], a1[1], a1[2], a1[3], ak + aCol1);
                ldsm4(b0[0], b0[1], b0[2], b0[3], bBase + bCol[k]);
                ldsm4(b1[0], b1[1], b1[2], b1[3], bBase + 4096u + bCol[k]);
                mma16816(c[0], a0[0], a0[1], a0[2], a0[3], b0[0], b0[1]);
                mma16816(c[1], a0[0], a0[1], a0[2], a0[3], b0[2], b0[3]);
                mma16816(c[2], a0[0], a0[1], a0[2], a0[3], b1[0], b1[1]);
                mma16816(c[3], a0[0], a0[1], a0[2], a0[3], b1[2], b1[3]);
                mma16816(c[4], a1[0], a1[1], a1[2], a1[3], b0[0], b0[1]);
                mma16816(c[5], a1[0], a1[1], a1[2], a1[3], b0[2], b0[3]);
                mma16816(c[6], a1[0], a1[1], a1[2], a1[3], b1[0], b1[1]);
                mma16816(c[7], a1[0], a1[1], a1[2], a1[3], b1[2], b1[3]);
            }
        }

        // build A(fl+1) into alternate buffer
        if (fl < FH - 1) {
            const float* jw = (const float*)(cm + JW_OFF + (uint32_t)((fl + 1) & 1) * 1024);
            float2 xv = *(const float2*)(xs + (fl + 1) * 64 + 2 * rp);
            __half2 wh = *(__half2*)(wts + (fl + 1) * 64 + 2 * rp);
            float2 wv = __half22float2(wh);
            char* ab = cm + AB_OFF + (uint32_t)((fl + 1) & 1) * ASLAB;
            #pragma unroll 8
            for (int j = 0; j < 16; j++) {
                int h = hblk * 16 + j;
                float2 jv = *(const float2*)(jw + 2 * h);
                float v0 = fmaf(xv.x, jv.x, jv.y);
                float v1 = fmaf(xv.y, jv.x, jv.y);
                float a0 = (v0 > 0.f ? v0 : (__expf(v0) - 1.f)) * wv.x;
                float a1 = (v1 > 0.f ? v1 : (__expf(v1) - 1.f)) * wv.y;
                uint32_t off = (uint32_t)h * 128u + (uint32_t)rp * 4u;
                *(__half2*)(ab + SWZA(off)) = __float22half2_rn(make_float2(a0, a1));
            }
        }
        CP_WAIT0();
    }

    // epilogue
    {
        const int g = lane >> 2, tig = lane & 3;
        #pragma unroll
        for (int mt = 0; mt < 2; mt++) {
            const int row0 = rbase + m0 + mt * 16 + g;
            #pragma unroll
            for (int nt = 0; nt < 4; nt++) {
                const int col = n0 + nt * 8 + 2 * tig;
                float* cc = c[mt * 4 + nt];
                *(float2*)(dst + row0 * HH + col)       = make_float2(cc[0], cc[1]);
                *(float2*)(dst + (row0 + 8) * HH + col) = make_float2(cc[2], cc[3]);
            }
        }
    }
}

// ---------------------------------------------------------------------------
// finish: out += g_part + w_t @ jb3. Grid 256 x 256, 32 rows each (2 CTAs/SM).
// ---------------------------------------------------------------------------
__global__ __launch_bounds__(256) void finish_kernel(const float* __restrict__ jb3,
                                                     float* __restrict__ out)
{
    extern __shared__ float fm[];
    float* wtT  = fm;          // [64 f][32 r] = 2048
    float* jb3s = fm + 2048;   // [64 f][128 k] = 8192
    const int tid = threadIdx.x;
    const int rbase = blockIdx.x * 32;
    const int ty = tid >> 4, tx = tid & 15;

    #pragma unroll
    for (int i = 0; i < 2; i++) {
        int q = tid + i * 256;          // 0..511
        int r = q >> 4, fc = q & 15;
        float4 wv = *(const float4*)(g_wt_buf + (rbase + r) * FF + fc * 4);
        wtT[(fc * 4 + 0) * 32 + r] = wv.x; wtT[(fc * 4 + 1) * 32 + r] = wv.y;
        wtT[(fc * 4 + 2) * 32 + r] = wv.z; wtT[(fc * 4 + 3) * 32 + r] = wv.w;
    }
    #pragma unroll
    for (int i = 0; i < 8; i++)
        ((float4*)jb3s)[tid + i * 256] = ((const float4*)jb3)[tid + i * 256];
    __syncthreads();

    unsigned long long acc[8];
    #pragma unroll
    for (int j = 0; j < 8; j++) acc[j] = 0ull;
    #pragma unroll 4
    for (int f = 0; f < FF; f++) {
        unsigned long long wp = *(const unsigned long long*)(wtT + f * 32 + ty * 2);
        float4 ja = *(const float4*)(jb3s + f * 128 + tx * 8);
        float4 jb = *(const float4*)(jb3s + f * 128 + tx * 8 + 4);
        float js[8] = {ja.x, ja.y, ja.z, ja.w, jb.x, jb.y, jb.z, jb.w};
        #pragma unroll
        for (int j = 0; j < 8; j++)
            ffma2(acc[j], wp, pk2(js[j]));
    }
    {
        float lo[8], hi[8];
        #pragma unroll
        for (int j = 0; j < 8; j++) up2(acc[j], lo[j], hi[j]);
        #pragma unroll
        for (int e = 0; e < 2; e++) {
            float* v = e ? hi : lo;
            int row = rbase + ty * 2 + e;
            float4* po = (float4*)(out + row * HH + tx * 8);
            const float4* pp = (const float4*)(g_part + row * HH + tx * 8);
            float4 o0 = po[0], o1 = po[1], p0 = pp[0], p1 = pp[1];
            po[0] = make_float4(o0.x + p0.x + v[0], o0.y + p0.y + v[1], o0.z + p0.z + v[2], o0.w + p0.w + v[3]);
            po[1] = make_float4(o1.x + p1.x + v[4], o1.y + p1.y + v[5], o1.z + p1.z + v[6], o1.w + p1.w + v[7]);
        }
    }
}

extern "C" void kernel_launch(void* const* d_in, const int* in_sizes, int n_in,
                              void* d_out, int out_size) {
    const float* x   = (const float*)d_in[0];
    const float* s   = (const float*)d_in[1];
    const float* w1  = (const float*)d_in[2];
    const float* b1  = (const float*)d_in[3];
    const float* w2  = (const float*)d_in[4];
    const float* b2  = (const float*)d_in[5];
    const float* w3  = (const float*)d_in[6];
    const float* b3  = (const float*)d_in[7];
    const float* jw1 = (const float*)d_in[8];
    const float* jb1 = (const float*)d_in[9];
    const float* jw3 = (const float*)d_in[10];
    const float* jb3 = (const float*)d_in[11];
    float* out = (float*)d_out;

    cudaFuncSetAttribute(prep_gating_kernel, cudaFuncAttributeMaxDynamicSharedMemorySize, SMEMG);
    cudaFuncSetAttribute(combine_kernel,     cudaFuncAttributeMaxDynamicSharedMemorySize, SMEM2);
    cudaFuncSetAttribute(finish_kernel,      cudaFuncAttributeMaxDynamicSharedMemorySize, 40960);

    prep_gating_kernel<<<128, 256, SMEMG>>>(jw3, x, s, w1, b1, w2, b2, w3, b3);
    combine_kernel<<<256, 256, SMEM2>>>(x, jw1, jb1, out);
    finish_kernel<<<256, 256, 40960>>>(jb3, out);
}

// round 17
// speedup vs baseline: 1.0846x; 1.0846x over previous
#include <cuda_runtime.h>
#include <cuda_fp16.h>
#include <stdint.h>

#define FF 64
#define HH 128
#define NROW 8192
#define FH 32
#define BSLAB 32768           // B slab: 128 n-rows * 256B, swizzled
#define ASLAB 16384           // A tile: 128 h-rows * 128B, swizzled

__device__ float g_gbuf[NROW * FF];     // raw gating logits
__device__ __align__(16) unsigned char g_Bt[FF * BSLAB];  // jw3^T fp16 [f][n][h], swizzled
__device__ __align__(16) unsigned char g_Bj[16384];       // jb3^T fp16 [col][f], pitch 128B, SWZA

// ---------------- helpers ----------------
__device__ __forceinline__ uint32_t smem_u32(const void* p) {
    uint32_t a;
    asm("{ .reg .u64 t; cvta.to.shared.u64 t, %1; cvt.u32.u64 %0, t; }" : "=r"(a) : "l"(p));
    return a;
}
__device__ __forceinline__ void ffma2(unsigned long long& d, unsigned long long a, unsigned long long b) {
    asm("fma.rn.f32x2 %0, %1, %2, %0;" : "+l"(d) : "l"(a), "l"(b));
}
__device__ __forceinline__ unsigned long long pk2(float v) {
    unsigned long long r; asm("mov.b64 %0, {%1, %1};" : "=l"(r) : "f"(v)); return r;
}
__device__ __forceinline__ void up2(unsigned long long v, float& lo, float& hi) {
    asm("mov.b64 {%0, %1}, %2;" : "=f"(lo), "=f"(hi) : "l"(v));
}
#define CP16(dst, src)  asm volatile("cp.async.cg.shared.global [%0], [%1], 16;" :: "r"((uint32_t)(dst)), "l"(src) : "memory")
#define CP_COMMIT()     asm volatile("cp.async.commit_group;" ::: "memory")
#define CP_WAIT0()      asm volatile("cp.async.wait_group 0;" ::: "memory")
#define REDADD(p, v)    asm volatile("red.global.add.f32 [%0], %1;" :: "l"(p), "f"(v) : "memory")

// swizzles: A rows are 128B (h-major), B rows are 256B (n-major)
#define SWZA(o) ((o) ^ ((((o) >> 7) & 7) << 4))
#define SWZB(o) ((o) ^ ((((o) >> 8) & 7) << 4))

__device__ __forceinline__ void ldsm4t(uint32_t& r0, uint32_t& r1, uint32_t& r2, uint32_t& r3, uint32_t a) {
    asm volatile("ldmatrix.sync.aligned.m8n8.x4.trans.shared.b16 {%0,%1,%2,%3}, [%4];"
                 : "=r"(r0), "=r"(r1), "=r"(r2), "=r"(r3) : "r"(a));
}
__device__ __forceinline__ void ldsm4(uint32_t& r0, uint32_t& r1, uint32_t& r2, uint32_t& r3, uint32_t a) {
    asm volatile("ldmatrix.sync.aligned.m8n8.x4.shared.b16 {%0,%1,%2,%3}, [%4];"
                 : "=r"(r0), "=r"(r1), "=r"(r2), "=r"(r3) : "r"(a));
}
__device__ __forceinline__ void mma16816(float* c, uint32_t a0, uint32_t a1, uint32_t a2, uint32_t a3,
                                         uint32_t b0, uint32_t b1) {
    asm volatile("mma.sync.aligned.m16n8k16.row.col.f32.f16.f16.f32 "
                 "{%0,%1,%2,%3}, {%4,%5,%6,%7}, {%8,%9}, {%0,%1,%2,%3};"
                 : "+f"(c[0]), "+f"(c[1]), "+f"(c[2]), "+f"(c[3])
                 : "r"(a0), "r"(a1), "r"(a2), "r"(a3), "r"(b0), "r"(b1));
}

// ---------------------------------------------------------------------------
// prep_gating: grid 128, one wave. All blocks zero their out slice.
// Blocks 0-63 prep jw3 f-slab; block 64 builds g_Bj; then all run gating.
// Gating smem (164 KB, 1 CTA/SM):
//   xT 0 | sT 4096 | w1s 8192 | w2s 16384 | G1T 24576 (pitch 72) | w3s 33792
// ---------------------------------------------------------------------------
#define SMEMG 167936

__global__ __launch_bounds__(256) void prep_gating_kernel(
    const float* __restrict__ jw3, const float* __restrict__ jb3,
    const float* __restrict__ x, const float* __restrict__ s,
    const float* __restrict__ w1, const float* __restrict__ b1,
    const float* __restrict__ w2, const float* __restrict__ b2,
    const float* __restrict__ w3, const float* __restrict__ b3,
    float* __restrict__ out)
{
    extern __shared__ float gm[];
    const int tid = threadIdx.x;

    // zero out slice [blk*64 rows x 128]
    {
        float4 z = make_float4(0.f, 0.f, 0.f, 0.f);
        float4* o4 = (float4*)out + blockIdx.x * 2048;
        #pragma unroll
        for (int i = 0; i < 8; i++) o4[tid + i * 256] = z;
    }

    if (blockIdx.x < 64) {
        // ---- prep: jw3[f][h][k] -> g_Bt[f][n=k][h] fp16, swizzled ----
        char* psm = (char*)(gm + 33792);   // w3s region scratch
        const int f = blockIdx.x;
        const int h = tid >> 1, khalf = tid & 1;
        #pragma unroll 4
        for (int j = 0; j < 16; j++) {
            float4 v = *(const float4*)(jw3 + f * 16384 + h * 128 + khalf * 64 + j * 4);
            int k0 = khalf * 64 + j * 4;
            float vv[4] = {v.x, v.y, v.z, v.w};
            #pragma unroll
            for (int e = 0; e < 4; e++) {
                uint32_t off = (uint32_t)(k0 + e) * 256u + (uint32_t)h * 2u;
                *(__half*)(psm + SWZB(off)) = __float2half_rn(vv[e]);
            }
        }
        __syncthreads();
        float4* dst = (float4*)(g_Bt + f * BSLAB);
        const float4* src = (const float4*)psm;
        #pragma unroll
        for (int i = 0; i < 8; i++)
            dst[tid + i * 256] = src[tid + i * 256];
        __syncthreads();   // prep done; w3s region free for w3 staging
    } else if (blockIdx.x == 64) {
        // ---- g_Bj: jb3[f][col] -> [col][f] fp16, pitch 128B, SWZA ----
        const int i0 = tid * 32;
        #pragma unroll 8
        for (int i = 0; i < 32; i++) {
            int idx = i0 + i;                 // 0..8191
            int col = idx >> 6, f = idx & 63;
            uint32_t off = (uint32_t)col * 128u + (uint32_t)f * 2u;
            *(__half*)(g_Bj + SWZA(off)) = __float2half_rn(jb3[f * HH + col]);
        }
    }

    // ---- gating: 64 rows -> raw logits g_gbuf ----
    float* xT  = gm;             // [64 f][64 r]
    float* sT  = gm + 4096;
    float* w1s = gm + 8192;      // [64 f][128 h]
    float* w2s = gm + 16384;
    float* G1T = gm + 24576;     // [128 h][72]
    float* w3s = gm + 33792;     // [128 h][64 f]
    const int rbase = blockIdx.x * 64;
    const int ty = tid >> 4, tx = tid & 15;

    {
        const uint32_t smw = smem_u32(gm) + 32768u;     // w1s byte base
        const uint32_t smw3 = smem_u32(gm) + 135168u;   // w3s byte base
        #pragma unroll
        for (int i = 0; i < 8; i++) {
            CP16(smw + (uint32_t)(tid + i * 256) * 16u, (const char*)w1 + (tid + i * 256) * 16);
            CP16(smw + 32768u + (uint32_t)(tid + i * 256) * 16u, (const char*)w2 + (tid + i * 256) * 16);
            CP16(smw3 + (uint32_t)(tid + i * 256) * 16u, (const char*)w3 + (tid + i * 256) * 16);
        }
        CP_COMMIT();
    }
    #pragma unroll
    for (int i = 0; i < 4; i++) {
        int q = tid + i * 256;
        int r = q >> 4, fc = q & 15;
        float4 xv = *(const float4*)(x + (rbase + r) * FF + fc * 4);
        float4 sv = *(const float4*)(s + (rbase + r) * FF + fc * 4);
        xT[(fc * 4 + 0) * 64 + r] = xv.x; xT[(fc * 4 + 1) * 64 + r] = xv.y;
        xT[(fc * 4 + 2) * 64 + r] = xv.z; xT[(fc * 4 + 3) * 64 + r] = xv.w;
        sT[(fc * 4 + 0) * 64 + r] = sv.x; sT[(fc * 4 + 1) * 64 + r] = sv.y;
        sT[(fc * 4 + 2) * 64 + r] = sv.z; sT[(fc * 4 + 3) * 64 + r] = sv.w;
    }
    CP_WAIT0();
    __syncthreads();

    unsigned long long acc[2][8];
    #pragma unroll
    for (int i = 0; i < 2; i++)
        #pragma unroll
        for (int j = 0; j < 8; j++) acc[i][j] = 0ull;

    #pragma unroll 4
    for (int f = 0; f < FF; f++) {
        ulonglong2 xv = *(const ulonglong2*)(xT + f * 64 + ty * 4);
        ulonglong2 sv = *(const ulonglong2*)(sT + f * 64 + ty * 4);
        float4 wa = *(const float4*)(w1s + f * HH + tx * 8);
        float4 wb = *(const float4*)(w1s + f * HH + tx * 8 + 4);
        float4 va = *(const float4*)(w2s + f * HH + tx * 8);
        float4 vb = *(const float4*)(w2s + f * HH + tx * 8 + 4);
        float ws[8] = {wa.x, wa.y, wa.z, wa.w, wb.x, wb.y, wb.z, wb.w};
        float vs[8] = {va.x, va.y, va.z, va.w, vb.x, vb.y, vb.z, vb.w};
        unsigned long long xp[2] = {xv.x, xv.y}, sp[2] = {sv.x, sv.y};
        #pragma unroll
        for (int j = 0; j < 8; j++) {
            unsigned long long wj = pk2(ws[j]), vj = pk2(vs[j]);
            #pragma unroll
            for (int i = 0; i < 2; i++) { ffma2(acc[i][j], xp[i], wj); ffma2(acc[i][j], sp[i], vj); }
        }
    }
    #pragma unroll
    for (int j = 0; j < 8; j++) {
        int h = tx * 8 + j;
        float bb = b1[h] + b2[h];
        float v[4];
        up2(acc[0][j], v[0], v[1]); up2(acc[1][j], v[2], v[3]);
        float4 o; float* po = &o.x;
        #pragma unroll
        for (int i = 0; i < 4; i++) {
            float t = v[i] + bb;
            po[i] = t > 0.f ? t : (__expf(t) - 1.f);
        }
        *(float4*)(G1T + h * 72 + ty * 4) = o;
    }
    __syncthreads();

    unsigned long long a2[2][4];
    #pragma unroll
    for (int i = 0; i < 2; i++)
        #pragma unroll
        for (int j = 0; j < 4; j++) a2[i][j] = 0ull;
    #pragma unroll 8
    for (int h = 0; h < HH; h++) {
        ulonglong2 av = *(const ulonglong2*)(G1T + h * 72 + ty * 4);
        float4 wv = *(const float4*)(w3s + h * FF + tx * 4);
        float ws[4] = {wv.x, wv.y, wv.z, wv.w};
        unsigned long long ap[2] = {av.x, av.y};
        #pragma unroll
        for (int j = 0; j < 4; j++) {
            unsigned long long wj = pk2(ws[j]);
            ffma2(a2[0][j], ap[0], wj);
            ffma2(a2[1][j], ap[1], wj);
        }
    }
    float b3v[4] = {b3[tx * 4], b3[tx * 4 + 1], b3[tx * 4 + 2], b3[tx * 4 + 3]};
    #pragma unroll
    for (int p = 0; p < 2; p++) {
        float lo[4], hi[4];
        #pragma unroll
        for (int j = 0; j < 4; j++) up2(a2[p][j], lo[j], hi[j]);
        int r0 = rbase + ty * 4 + p * 2;
        *(float4*)(g_gbuf + r0 * FF + tx * 4) =
            make_float4(lo[0] + b3v[0], lo[1] + b3v[1], lo[2] + b3v[2], lo[3] + b3v[3]);
        *(float4*)(g_gbuf + (r0 + 1) * FF + tx * 4) =
            make_float4(hi[0] + b3v[0], hi[1] + b3v[1], hi[2] + b3v[2], hi[3] + b3v[3]);
    }
}

// ---------------------------------------------------------------------------
// combine: grid 256 = 128 row-tiles x 2 f-halves, 64 rows, 32 f. 2 CTAs/SM.
// Fused softmax; jb3 epilogue MMA; red.global.add epilogue (out pre-zeroed).
// smem: A 2x16384 | B 2x32768 | XS 8192 | WT 4096 (fp16) | JWC 2x1024
// ---------------------------------------------------------------------------
#define AB_OFF  0u
#define BB_OFF  32768u
#define XS_OFF  98304u
#define WT_OFF  106496u
#define JW_OFF  110592u
#define SMEM2   112640u

__global__ __launch_bounds__(256, 2) void combine_kernel(
    const float* __restrict__ x,
    const float* __restrict__ jw1, const float* __restrict__ jb1,
    float* __restrict__ out)
{
    extern __shared__ char cm[];
    const uint32_t smb = smem_u32(cm);
    float* xs = (float*)(cm + XS_OFF);       // [32 f][64 r] fp32
    __half* wts = (__half*)(cm + WT_OFF);    // [32 f][64 r] fp16
    const int tid = threadIdx.x;
    const int wid = tid >> 5, lane = tid & 31;
    const int rt = blockIdx.x >> 1, half = blockIdx.x & 1;
    const int rbase = rt * 64, fbase = half * FH;
    const int gbase = (blockIdx.x >> 2) * 128;   // (b,a) group row base
    const int rhalf = rt & 1;                    // which 64-row half of the group

    // B(0) async copy
    {
        const unsigned char* src = g_Bt + fbase * BSLAB;
        #pragma unroll
        for (int i = 0; i < 8; i++)
            CP16(smb + BB_OFF + (tid + i * 256) * 16, src + (tid + i * 256) * 16);
        CP_COMMIT();
    }
    // stage raw logit column [32 f][128 t] into A-buf0 window (fp32, 16KB)
    {
        float* gcol = (float*)(cm + AB_OFF);
        #pragma unroll
        for (int i = 0; i < 4; i++) {
            int q = tid + i * 256;               // 0..1023
            int r = q >> 3, fs = q & 7;
            float4 gv = *(const float4*)(g_gbuf + (gbase + r) * FF + fbase + fs * 4);
            gcol[(fs * 4 + 0) * 128 + r] = gv.x;
            gcol[(fs * 4 + 1) * 128 + r] = gv.y;
            gcol[(fs * 4 + 2) * 128 + r] = gv.z;
            gcol[(fs * 4 + 3) * 128 + r] = gv.w;
        }
    }
    // stage xs (fp32) transposed [f][r]
    #pragma unroll
    for (int i = 0; i < 2; i++) {
        int q = tid + i * 256;               // 0..511
        int r = q >> 3, fs = q & 7;
        float4 xv = *(const float4*)(x + (rbase + r) * FF + fbase + fs * 4);
        xs[(fs * 4 + 0) * 64 + r] = xv.x; xs[(fs * 4 + 1) * 64 + r] = xv.y;
        xs[(fs * 4 + 2) * 64 + r] = xv.z; xs[(fs * 4 + 3) * 64 + r] = xv.w;
    }
    // jwc(0), jwc(1)
    if (tid < 128) {
        float* j0 = (float*)(cm + JW_OFF);
        float* j1 = (float*)(cm + JW_OFF + 1024);
        j0[2 * tid]     = jw1[(fbase + 0) * HH + tid];
        j0[2 * tid + 1] = jb1[(fbase + 0) * HH + tid];
        j1[2 * tid]     = jw1[(fbase + 1) * HH + tid];
        j1[2 * tid + 1] = jb1[(fbase + 1) * HH + tid];
    }
    __syncthreads();

    // fused softmax over 128 t per f (32 f x 8 lanes, 16 t each)
    {
        const float* gcol = (const float*)(cm + AB_OFF);
        const int fc = tid >> 3, sub = tid & 7;
        float vals[16], m = -1e30f;
        #pragma unroll
        for (int j = 0; j < 16; j++) {
            vals[j] = gcol[fc * 128 + sub * 16 + j];
            m = fmaxf(m, vals[j]);
        }
        #pragma unroll
        for (int o = 1; o < 8; o <<= 1) m = fmaxf(m, __shfl_xor_sync(0xffffffffu, m, o, 8));
        float ssum = 0.f;
        #pragma unroll
        for (int j = 0; j < 16; j++) { vals[j] = __expf(vals[j] - m); ssum += vals[j]; }
        #pragma unroll
        for (int o = 1; o < 8; o <<= 1) ssum += __shfl_xor_sync(0xffffffffu, ssum, o, 8);
        float rinv = 1.f / ssum;
        #pragma unroll
        for (int j = 0; j < 16; j++) {
            int t = sub * 16 + j;
            if ((t >> 6) == rhalf)
                wts[fc * 64 + (t & 63)] = __float2half_rn(vals[j] * rinv);
        }
    }
    __syncthreads();   // gcol reads done; A-buf0 free

    const int rp = tid & 31, hblk = tid >> 5;   // rows 2rp,2rp+1 ; h = hblk*16..
    // build A(0) into buf 0 (layout [h][r] fp16, swizzled 128B rows)
    {
        const float* jw = (const float*)(cm + JW_OFF);
        float2 xv = *(const float2*)(xs + 2 * rp);
        __half2 wh = *(__half2*)(wts + 2 * rp);
        float2 wv = __half22float2(wh);
        #pragma unroll 8
        for (int j = 0; j < 16; j++) {
            int h = hblk * 16 + j;
            float2 jv = *(const float2*)(jw + 2 * h);
            float v0 = fmaf(xv.x, jv.x, jv.y);
            float v1 = fmaf(xv.y, jv.x, jv.y);
            float a0 = (v0 > 0.f ? v0 : (__expf(v0) - 1.f)) * wv.x;
            float a1 = (v1 > 0.f ? v1 : (__expf(v1) - 1.f)) * wv.y;
            uint32_t off = (uint32_t)h * 128u + (uint32_t)rp * 4u;
            *(__half2*)(cm + AB_OFF + SWZA(off)) = __float22half2_rn(make_float2(a0, a1));
        }
    }
    CP_WAIT0();

    // ---- MMA geometry: 2 m-groups x 4 n-groups, precomputed swizzled cols ----
    const int mg = wid & 1, ng = wid >> 1;
    const int m0 = mg * 32, n0 = ng * 32;
    const int lr = lane & 7, sel0 = (lane >> 3) & 1, sel1 = (lane >> 4) & 1;
    const uint32_t aRow = (uint32_t)(sel1 * 8 + lr) * 128u;
    const uint32_t aXor = (uint32_t)lr << 4;
    const uint32_t aCol0 = ((uint32_t)(m0 * 2 + sel0 * 16)) ^ aXor;
    const uint32_t aCol1 = ((uint32_t)(m0 * 2 + 32 + sel0 * 16)) ^ aXor;
    const uint32_t bRow = (uint32_t)(lr + sel1 * 8 + n0);
    const uint32_t bXor = (bRow & 7u) << 4;
    const uint32_t bRowOff = bRow * 256u;
    uint32_t bCol[8];
    #pragma unroll
    for (int k = 0; k < 8; k++)
        bCol[k] = (((uint32_t)(sel0 * 16)) + (uint32_t)k * 32u) ^ bXor;

    float c[8][4];
    #pragma unroll
    for (int n = 0; n < 8; n++)
        #pragma unroll
        for (int e = 0; e < 4; e++) c[n][e] = 0.f;

    for (int fl = 0; fl < FH; fl++) {
        __syncthreads();   // A(fl) built, B(fl) arrived
        if (fl < FH - 2 && tid < 128) {
            float* jn = (float*)(cm + JW_OFF + (uint32_t)(fl & 1) * 1024);
            jn[2 * tid]     = jw1[(fbase + fl + 2) * HH + tid];
            jn[2 * tid + 1] = jb1[(fbase + fl + 2) * HH + tid];
        }
        // prefetch B(fl+1), or g_Bj slab into B-buf0 on last iter
        if (fl < FH - 1) {
            const unsigned char* src = g_Bt + (fbase + fl + 1) * BSLAB;
            uint32_t dstb = smb + BB_OFF + (uint32_t)((fl + 1) & 1) * BSLAB;
            #pragma unroll
            for (int i = 0; i < 8; i++)
                CP16(dstb + (tid + i * 256) * 16, src + (tid + i * 256) * 16);
            CP_COMMIT();
        } else {
            #pragma unroll
            for (int i = 0; i < 4; i++)
                CP16(smb + BB_OFF + (tid + i * 256) * 16, g_Bj + (tid + i * 256) * 16);
            CP_COMMIT();
        }

        // MMA(fl): k-major, 4 loads + 8 HMMA per k
        {
            const uint32_t aBase = smb + AB_OFF + (uint32_t)(fl & 1) * ASLAB + aRow;
            const uint32_t bBase = smb + BB_OFF + (uint32_t)(fl & 1) * BSLAB + bRowOff;
            #pragma unroll
            for (int k = 0; k < 8; k++) {
                uint32_t a0[4], a1[4], b0[4], b1[4];
                const uint32_t ak = aBase + (uint32_t)k * 2048u;
                ldsm4t(a0[0], a0[1], a0[2], a0[3], ak + aCol0);
                ldsm4t(a1[0], a1[1], a1[2], a1[3], ak + aCol1);
                ldsm4(b0[0], b0[1], b0[2], b0[3], bBase + bCol[k]);
                ldsm4(b1[0], b1[1], b1[2], b1[3], bBase + 4096u + bCol[k]);
                mma16816(c[0], a0[0], a0[1], a0[2], a0[3], b0[0], b0[1]);
                mma16816(c[1], a0[0], a0[1], a0[2], a0[3], b0[2], b0[3]);
                mma16816(c[2], a0[0], a0[1], a0[2], a0[3], b1[0], b1[1]);
                mma16816(c[3], a0[0], a0[1], a0[2], a0[3], b1[2], b1[3]);
                mma16816(c[4], a1[0], a1[1], a1[2], a1[3], b0[0], b0[1]);
                mma16816(c[5], a1[0], a1[1], a1[2], a1[3], b0[2], b0[3]);
                mma16816(c[6], a1[0], a1[1], a1[2], a1[3], b1[0], b1[1]);
                mma16816(c[7], a1[0], a1[1], a1[2], a1[3], b1[2], b1[3]);
            }
        }

        if (fl < FH - 1) {
            const float* jw = (const float*)(cm + JW_OFF + (uint32_t)((fl + 1) & 1) * 1024);
            float2 xv = *(const float2*)(xs + (fl + 1) * 64 + 2 * rp);
            __half2 wh = *(__half2*)(wts + (fl + 1) * 64 + 2 * rp);
            float2 wv = __half22float2(wh);
            char* ab = cm + AB_OFF + (uint32_t)((fl + 1) & 1) * ASLAB;
            #pragma unroll 8
            for (int j = 0; j < 16; j++) {
                int h = hblk * 16 + j;
                float2 jv = *(const float2*)(jw + 2 * h);
                float v0 = fmaf(xv.x, jv.x, jv.y);
                float v1 = fmaf(xv.y, jv.x, jv.y);
                float a0 = (v0 > 0.f ? v0 : (__expf(v0) - 1.f)) * wv.x;
                float a1 = (v1 > 0.f ? v1 : (__expf(v1) - 1.f)) * wv.y;
                uint32_t off = (uint32_t)h * 128u + (uint32_t)rp * 4u;
                *(__half2*)(ab + SWZA(off)) = __float22half2_rn(make_float2(a0, a1));
            }
        }
        CP_WAIT0();
    }

    // A_x = wts copy into A-buf0 rows 0..31 ([f][r] fp16, SWZA)
    {
        const __half2* wsrc = (const __half2*)wts;
        #pragma unroll
        for (int i = 0; i < 4; i++) {
            int q = tid + i * 256;          // 0..1023 half2 units
            int f = q >> 5, r2 = q & 31;
            uint32_t off = (uint32_t)f * 128u + (uint32_t)r2 * 4u;
            *(__half2*)(cm + AB_OFF + SWZA(off)) = wsrc[f * 32 + r2];
        }
    }
    __syncthreads();   // A_x + g_Bj (B-buf0) visible

    // jb3 epilogue MMA: K=32 (2 k-tiles), B pitch 128B
    {
        const uint32_t aBase = smb + AB_OFF + aRow;
        const uint32_t bjBase = smb + BB_OFF + bRow * 128u;
        #pragma unroll
        for (int kk = 0; kk < 2; kk++) {
            uint32_t colOff = (uint32_t)(sel0 * 16 + kk * 32 + fbase * 2);
            uint32_t a0[4], a1[4], b0[4], b1[4];
            const uint32_t ak = aBase + (uint32_t)kk * 2048u;
            ldsm4t(a0[0], a0[1], a0[2], a0[3], ak + aCol0);
            ldsm4t(a1[0], a1[1], a1[2], a1[3], ak + aCol1);
            ldsm4(b0[0], b0[1], b0[2], b0[3], bjBase + (colOff ^ bXor));
            ldsm4(b1[0], b1[1], b1[2], b1[3], bjBase + 2048u + (colOff ^ bXor));
            mma16816(c[0], a0[0], a0[1], a0[2], a0[3], b0[0], b0[1]);
            mma16816(c[1], a0[0], a0[1], a0[2], a0[3], b0[2], b0[3]);
            mma16816(c[2], a0[0], a0[1], a0[2], a0[3], b1[0], b1[1]);
            mma16816(c[3], a0[0], a0[1], a0[2], a0[3], b1[2], b1[3]);
            mma16816(c[4], a1[0], a1[1], a1[2], a1[3], b0[0], b0[1]);
            mma16816(c[5], a1[0], a1[1], a1[2], a1[3], b0[2], b0[3]);
            mma16816(c[6], a1[0], a1[1], a1[2], a1[3], b1[0], b1[1]);
            mma16816(c[7], a1[0], a1[1], a1[2], a1[3], b1[2], b1[3]);
        }
    }

    // epilogue: red.global.add into pre-zeroed out
    {
        const int g = lane >> 2, tig = lane & 3;
        #pragma unroll
        for (int mt = 0; mt < 2; mt++) {
            const int row0 = rbase + m0 + mt * 16 + g;
            #pragma unroll
            for (int nt = 0; nt < 4; nt++) {
                const int col = n0 + nt * 8 + 2 * tig;
                float* cc = c[mt * 4 + nt];
                float* p0 = out + row0 * HH + col;
                float* p1 = out + (row0 + 8) * HH + col;
                REDADD(p0, cc[0]);
                REDADD(p0 + 1, cc[1]);
                REDADD(p1, cc[2]);
                REDADD(p1 + 1, cc[3]);
            }
        }
    }
}

extern "C" void kernel_launch(void* const* d_in, const int* in_sizes, int n_in,
                              void* d_out, int out_size) {
    const float* x   = (const float*)d_in[0];
    const float* s   = (const float*)d_in[1];
    const float* w1  = (const float*)d_in[2];
    const float* b1  = (const float*)d_in[3];
    const float* w2  = (const float*)d_in[4];
    const float* b2  = (const float*)d_in[5];
    const float* w3  = (const float*)d_in[6];
    const float* b3  = (const float*)d_in[7];
    const float* jw1 = (const float*)d_in[8];
    const float* jb1 = (const float*)d_in[9];
    const float* jw3 = (const float*)d_in[10];
    const float* jb3 = (const float*)d_in[11];
    float* out = (float*)d_out;

    cudaFuncSetAttribute(prep_gating_kernel, cudaFuncAttributeMaxDynamicSharedMemorySize, SMEMG);
    cudaFuncSetAttribute(combine_kernel,     cudaFuncAttributeMaxDynamicSharedMemorySize, SMEM2);

    prep_gating_kernel<<<128, 256, SMEMG>>>(jw3, jb3, x, s, w1, b1, w2, b2, w3, b3, out);
    combine_kernel<<<256, 256, SMEM2>>>(x, jw1, jb1, out);
}